// round 14
// baseline (speedup 1.0000x reference)
#include <cuda_runtime.h>

// SAXS P(r) L1 loss — Round 10.
// vs R9: (1) private hist cut to 100 words (lo<=97, d<=48.9A; 0.74% of pairs
// -> parity u64 smem-ATOMS fallback) => 55.6KB/block => 4 blocks/SM, 16 warps;
// (2) Gram-trick distance (s=|r|^2 precomputed in .w): 5 FP/pair vs 6;
// (3) flush bounds adjusted (merge word 98 / diag word 99 dead).
// Inner loop otherwise R5/R9: dual-field u32 private smem hist, 1 RMW/pair,
// magic rounding, MLP=2 + equal-offset merge (lost-update safe).

namespace {
constexpr int   kNBins      = 201;
constexpr int   kNAtoms     = 9472;                       // 256*37
constexpr int   kTile       = 128;
constexpr int   kNTiles     = kNAtoms / kTile;            // 74
constexpr int   kNPairTiles = kNTiles * (kNTiles + 1) / 2;   // 2775
constexpr int   kBlocksX    = 592;                        // 4 blocks/SM * 148 SM
constexpr int   kThreads    = 128;
constexpr float kPre        = 512.0f;                     // 256 / STEP
constexpr float kClampT     = 52223.0f;                   // word 203 (dropped)
constexpr int   kWords      = 100;   // lo 0..97 live, 98 merge-dead, 99 diag-dead
constexpr int   kHistU32    = kWords * kThreads;          // 12800 (51200 B)
constexpr int   kParU32     = 2 * 208;                    // pA[208], pB[208]
constexpr int   kSmemBytes  = (kHistU32 + kParU32) * 4 + 256 * 16;   // 56960
constexpr unsigned kLiveMaxOff = 97u * 512u;
constexpr unsigned kMergeOff   = 98u * 512u;
constexpr unsigned kDiagOff    = 99u * 512u;
}

__device__ float4       g_pos[2][kNAtoms];   // (x,y,z,|r|^2), prescaled
__device__ unsigned int g_hist[2][256];
__device__ unsigned int g_done;

// ---------------------------------------------------------------------------
__global__ void prepack_kernel(const float* __restrict__ pred,
                               const float* __restrict__ tru,
                               const float* __restrict__ mask) {
    int i = blockIdx.x * blockDim.x + threadIdx.x;
    if (i == 0) g_done = 0u;
    if (i < 512) ((unsigned int*)g_hist)[i] = 0u;
    if (i >= kNAtoms) return;
    float m = mask[i];
    if (m != 0.0f) {
        float px = pred[3*i+0]*kPre, py = pred[3*i+1]*kPre, pz = pred[3*i+2]*kPre;
        float txx = tru[3*i+0]*kPre, tyy = tru[3*i+1]*kPre, tzz = tru[3*i+2]*kPre;
        g_pos[0][i] = make_float4(px, py, pz, fmaf(px,px,fmaf(py,py,pz*pz)));
        g_pos[1][i] = make_float4(txx, tyy, tzz, fmaf(txx,txx,fmaf(tyy,tyy,tzz*tzz)));
    } else {
        float dx = 1.0e8f + (float)i * 2.0e5f;   // displaced -> clamp -> dropped
        g_pos[0][i] = make_float4(dx, 0.f, 0.f, dx * dx);
        g_pos[1][i] = make_float4(dx, 0.f, 0.f, dx * dx);
    }
}

// ---------------------------------------------------------------------------
__device__ __forceinline__ void decode_tile(int p, int& bi, int& bj) {
    double Td = (double)kNTiles;
    int b = (int)(((2.0 * Td + 1.0) -
                   sqrt((2.0 * Td + 1.0) * (2.0 * Td + 1.0) - 8.0 * (double)p)) * 0.5);
    if (b < 0) b = 0;
    if (b > kNTiles - 1) b = kNTiles - 1;
    while (b * (2 * kNTiles - b + 1) / 2 > p) --b;
    while ((b + 1) * (2 * kNTiles - b) / 2 <= p) ++b;
    bi = b;
    bj = b + (p - b * (2 * kNTiles - b + 1) / 2);
}

// Rare (word 98..203): parity-packed u64 smem atomic. Adds (256-q) to bin w,
// q to bin w+1. Flush: bin b += pA[b] + pB[b+1].
__device__ __forceinline__ void rare_add(unsigned* pA, unsigned* pB,
                                         unsigned w, unsigned q) {
    unsigned long long v = ((unsigned long long)q << 32)
                         | (unsigned long long)(256u - q);
    unsigned* addr = (w & 1u) ? (pB + w + 1) : (pA + w);
    atomicAdd((unsigned long long*)addr, v);
}

// Two pairs: Gram-trick distance, magic rounding, 1 RMW/pair, kill-safe rare.
__device__ __forceinline__ void process2(char* hb, unsigned* pA, unsigned* pB,
                                         float ax, float ay, float az, float as,
                                         const float4 j0, const float4 j1,
                                         bool k0, bool k1) {
    float e0 = fmaf(ax, j0.x, fmaf(ay, j0.y, az * j0.z));
    float e1 = fmaf(ax, j1.x, fmaf(ay, j1.y, az * j1.z));
    float d20 = fmaf(-2.0f, e0, as + j0.w);
    float d21 = fmaf(-2.0f, e1, as + j1.w);
    float t0 = fminf(d20 * rsqrtf(d20), kClampT);    // d*256/STEP; NaN -> clamp
    float t1 = fminf(d21 * rsqrtf(d21), kClampT);
    unsigned b0 = __float_as_uint(t0 + 12582912.0f); // rn(t) in low mantissa
    unsigned b1 = __float_as_uint(t1 + 12582912.0f);
    unsigned q0 = b0 & 255u, q1 = b1 & 255u;
    unsigned off0 = (b0 & 0xFF00u) << 1;             // word * 512
    unsigned off1 = (b1 & 0xFF00u) << 1;
    bool rare0 = off0 > kLiveMaxOff;
    bool rare1 = off1 > kLiveMaxOff;
    if (k0) { off0 = kDiagOff; rare0 = false; }      // kill -> dead private word
    if (k1) { off1 = kDiagOff; rare1 = false; }
    unsigned val0 = q0 * 65535u + 256u;              // (256-q) | (q<<16)
    unsigned val1 = q1 * 65535u + 256u;
    if (!(rare0 || rare1)) {                         // hot path (~98.5% batches)
        if (off0 == off1) { val0 += val1; off1 = kMergeOff; }  // no lost update
        unsigned a0 = *(unsigned*)(hb + off0);
        unsigned a1 = *(unsigned*)(hb + off1);
        *(unsigned*)(hb + off0) = a0 + val0;
        *(unsigned*)(hb + off1) = a1 + val1;
    } else {
        if (rare0) rare_add(pA, pB, off0 >> 9, q0);
        else       *(unsigned*)(hb + off0) += val0;
        if (rare1) rare_add(pA, pB, off1 >> 9, q1);
        else       *(unsigned*)(hb + off1) += val1;
    }
}

// ---------------------------------------------------------------------------
__global__ __launch_bounds__(kThreads, 4)
void pair_hist_kernel(float* __restrict__ out) {
    extern __shared__ unsigned int smem[];
    unsigned int* hist = smem;                         // [100][128]
    unsigned int* pA   = smem + kHistU32;              // [208]
    unsigned int* pB   = pA + 208;                     // [208]
    float4* buf = (float4*)(pB + 208);                 // [256]

    const int s   = blockIdx.y;
    const int tid = threadIdx.x;
    const int tx  = tid & 15;     // cols tx*8 + v
    const int ty  = tid >> 4;     // rows ty*16 + u
    char* hb = (char*)hist + tid * 4;                  // bank = tid&31

#pragma unroll 4
    for (int w = 0; w < kWords; ++w) hist[(w << 7) + tid] = 0u;
    for (int k = tid; k < 2 * 208; k += kThreads) pA[k] = 0u;

    int p = blockIdx.x;
    int bi, bj;
    decode_tile(p, bi, bj);
    buf[tid]       = g_pos[s][bi * kTile + tid];
    buf[128 + tid] = g_pos[s][bj * kTile + tid];
    __syncthreads();

    for (;;) {
        const int pn = p + kBlocksX;
        const bool havenext = (pn < kNPairTiles);
        float4 na, nb; int bin_ = 0, bjn = 0;
        if (havenext) {                                // prefetch to registers
            decode_tile(pn, bin_, bjn);
            na = g_pos[s][bin_ * kTile + tid];
            nb = g_pos[s][bjn * kTile + tid];
        }

        const float4* ti = buf;
        const float4* tj = buf + 128;
        float4 rj[8];
#pragma unroll
        for (int v = 0; v < 8; ++v) rj[v] = tj[tx * 8 + v];

        if (bi != bj) {
            for (int u0 = 0; u0 < 16; u0 += 4) {
#pragma unroll
                for (int uu = 0; uu < 4; ++uu) {
                    float4 a4 = ti[ty * 16 + u0 + uu];
#pragma unroll
                    for (int v = 0; v < 8; v += 2)
                        process2(hb, pA, pB, a4.x, a4.y, a4.z, a4.w,
                                 rj[v], rj[v + 1], false, false);
                }
            }
        } else {
            for (int u0 = 0; u0 < 16; u0 += 4) {
#pragma unroll
                for (int uu = 0; uu < 4; ++uu) {
                    const int iu = ty * 16 + u0 + uu;
                    float4 a4 = ti[iu];
#pragma unroll
                    for (int v = 0; v < 8; v += 2) {
                        const int jv = tx * 8 + v;
                        process2(hb, pA, pB, a4.x, a4.y, a4.z, a4.w,
                                 rj[v], rj[v + 1], iu >= jv, iu >= jv + 1);
                    }
                }
            }
        }

        __syncthreads();
        if (!havenext) break;
        buf[tid]       = na;
        buf[128 + tid] = nb;
        __syncthreads();
        p = pn; bi = bin_; bj = bjn;
    }

    // ---- flush ----
    // Private dual-field: word w low -> bin w, high -> bin w+1 (w 0..97 live;
    // words 98/99 dead, never read).
    unsigned* slo = (unsigned*)buf;          // [100]
    unsigned* shi = slo + 100;               // [100]
    if (tid < kWords) {
        unsigned lo = 0, hi = 0;
        for (int i = 0; i < kThreads; ++i) {
            int t = (tid + i) & 127;                    // staggered, conflict-free
            unsigned v = hist[(tid << 7) + t];
            lo += v & 0xFFFFu;
            hi += v >> 16;
        }
        slo[tid] = lo; shi[tid] = hi;
    }
    __syncthreads();
#pragma unroll
    for (int c = 0; c < 2; ++c) {
        int b = tid + c * kThreads;
        if (b <= 201) {
            unsigned tot = pA[b] + pB[b + 1];           // rare parity bins
            if (b <= 97) tot += slo[b];
            if (b >= 1 && b <= 98) tot += shi[b - 1];   // words 0..97 high fields
            int dst = (b == 201) ? 200 : b;             // fold 201 -> 200
            if (tot) atomicAdd(&g_hist[s][dst], tot);
        }
    }

    // ---- last block finalizes ----
    __threadfence();
    __shared__ unsigned int ticket;
    __syncthreads();
    if (tid == 0) ticket = atomicAdd(&g_done, 1u);
    __syncthreads();
    if (ticket != 2u * kBlocksX - 1u) return;
    __threadfence();

    double* sh = (double*)smem;
    volatile unsigned int* gh = (volatile unsigned int*)g_hist;
    double h0a = (tid < kNBins) ? (double)gh[tid] : 0.0;
    double h0b = (tid + 128 < kNBins) ? (double)gh[tid + 128] : 0.0;
    double h1a = (tid < kNBins) ? (double)gh[256 + tid] : 0.0;
    double h1b = (tid + 128 < kNBins) ? (double)gh[256 + tid + 128] : 0.0;

    sh[tid] = h0a + h0b; __syncthreads();
    for (int o = 64; o > 0; o >>= 1) { if (tid < o) sh[tid] += sh[tid + o]; __syncthreads(); }
    double s0 = sh[0]; __syncthreads();

    sh[tid] = h1a + h1b; __syncthreads();
    for (int o = 64; o > 0; o >>= 1) { if (tid < o) sh[tid] += sh[tid + o]; __syncthreads(); }
    double s1 = sh[0]; __syncthreads();

    double inv0 = 1.0 / (s0 + 1e-12), inv1 = 1.0 / (s1 + 1e-12);
    sh[tid] = fabs(h0a * inv0 - h1a * inv1) + fabs(h0b * inv0 - h1b * inv1);
    __syncthreads();
    for (int o = 64; o > 0; o >>= 1) { if (tid < o) sh[tid] += sh[tid + o]; __syncthreads(); }

    if (tid == 0) out[0] = (float)sh[0];
}

// ---------------------------------------------------------------------------
extern "C" void kernel_launch(void* const* d_in, const int* in_sizes, int n_in,
                              void* d_out, int out_size) {
    (void)in_sizes; (void)n_in; (void)out_size;
    const float* pred = (const float*)d_in[0];
    const float* tru  = (const float*)d_in[1];
    const float* mask = (const float*)d_in[2];

    cudaFuncSetAttribute(pair_hist_kernel,
                         cudaFuncAttributeMaxDynamicSharedMemorySize, kSmemBytes);

    prepack_kernel<<<(kNAtoms + 255) / 256, 256>>>(pred, tru, mask);

    dim3 grid(kBlocksX, 2);
    pair_hist_kernel<<<grid, kThreads, kSmemBytes>>>((float*)d_out);
}

// round 15
// speedup vs baseline: 1.1753x; 1.1753x over previous
#include <cuda_runtime.h>

// SAXS P(r) L1 loss — Round 11.
// Platform = R9 (136-word dual-field private smem hist, 128 thr, 3 blocks/SM,
// 1 RMW/pair, magic rounding, MLP=2 + equal-offset merge). Instruction diet:
//  - half-Gram distance: coords prescaled by 512*sqrt(2), w=|r|^2/2 stored;
//    g = aw+jw - a.j (FADD + 3 FFMA w/ free negation); t = g*rsqrt(g) = 512*d.
//  - branchless rare routing: private off = umin(off, 68608) -> rare pairs
//    land in dead word 134; no flags/sels.
//  - single-sided rare fix-up branch per batch (flat u32 rare[] smem atomics,
//    executed on ~0.3% of warp-batches), placed BEFORE the merge.

namespace {
constexpr int   kNBins      = 201;
constexpr int   kNAtoms     = 9472;                       // 256*37
constexpr int   kTile       = 128;
constexpr int   kNTiles     = kNAtoms / kTile;            // 74
constexpr int   kNPairTiles = kNTiles * (kNTiles + 1) / 2;   // 2775
constexpr int   kBlocksX    = 444;                        // 3 blocks/SM * 148
constexpr int   kThreads    = 128;
constexpr float kPre        = 724.0773439350246f;         // 512*sqrt(2)
constexpr float kClampT     = 52223.0f;                   // word 203 (dropped)
constexpr int   kWords      = 136;   // 0..133 live, 134/135 dead
constexpr int   kHistU32    = kWords * kThreads;          // 17408 (69632 B)
constexpr int   kRareU32    = 208;                        // flat rare bins
constexpr int   kSmemBytes  = (kHistU32 + kRareU32) * 4 + 256 * 16;  // 74560
constexpr unsigned kLiveMax  = 68096u;   // 133*512
constexpr unsigned kDead134  = 68608u;   // 134*512 (umin clamp target)
constexpr unsigned kDead135  = 69120u;   // 135*512 (merge redirect)
}

__device__ float4       g_pos[2][kNAtoms];   // (x,y,z,|r|^2/2), prescaled
__device__ unsigned int g_hist[2][256];
__device__ unsigned int g_done;

// ---------------------------------------------------------------------------
__global__ void prepack_kernel(const float* __restrict__ pred,
                               const float* __restrict__ tru,
                               const float* __restrict__ mask) {
    int i = blockIdx.x * blockDim.x + threadIdx.x;
    if (i == 0) g_done = 0u;
    if (i < 512) ((unsigned int*)g_hist)[i] = 0u;
    if (i >= kNAtoms) return;
    float m = mask[i];
    if (m != 0.0f) {
        float px = pred[3*i+0]*kPre, py = pred[3*i+1]*kPre, pz = pred[3*i+2]*kPre;
        float qx = tru [3*i+0]*kPre, qy = tru [3*i+1]*kPre, qz = tru [3*i+2]*kPre;
        g_pos[0][i] = make_float4(px, py, pz, 0.5f * fmaf(px,px,fmaf(py,py,pz*pz)));
        g_pos[1][i] = make_float4(qx, qy, qz, 0.5f * fmaf(qx,qx,fmaf(qy,qy,qz*qz)));
    } else {
        float dx = 1.0e8f + (float)i * 2.0e5f;   // displaced -> clamp -> dropped
        g_pos[0][i] = make_float4(dx, 0.f, 0.f, 0.5f * dx * dx);
        g_pos[1][i] = make_float4(dx, 0.f, 0.f, 0.5f * dx * dx);
    }
}

// ---------------------------------------------------------------------------
__device__ __forceinline__ void decode_tile(int p, int& bi, int& bj) {
    double Td = (double)kNTiles;
    int b = (int)(((2.0 * Td + 1.0) -
                   sqrt((2.0 * Td + 1.0) * (2.0 * Td + 1.0) - 8.0 * (double)p)) * 0.5);
    if (b < 0) b = 0;
    if (b > kNTiles - 1) b = kNTiles - 1;
    while (b * (2 * kNTiles - b + 1) / 2 > p) --b;
    while ((b + 1) * (2 * kNTiles - b) / 2 <= p) ++b;
    bi = b;
    bj = b + (p - b * (2 * kNTiles - b + 1) / 2);
}

// Two pairs. DIAG is compile-time; iu/jv only used when DIAG.
template <bool DIAG>
__device__ __forceinline__ void process2(char* hb, unsigned* rare,
                                         float ax, float ay, float az, float aw,
                                         const float4 j0, const float4 j1,
                                         int iu, int jv) {
    float g0 = fmaf(ax, -j0.x, fmaf(ay, -j0.y, fmaf(az, -j0.z, aw + j0.w)));
    float g1 = fmaf(ax, -j1.x, fmaf(ay, -j1.y, fmaf(az, -j1.z, aw + j1.w)));
    float t0 = fminf(g0 * rsqrtf(g0), kClampT);      // = 512*d; NaN -> clamp
    float t1 = fminf(g1 * rsqrtf(g1), kClampT);
    unsigned b0 = __float_as_uint(t0 + 12582912.0f); // rn(t) in low mantissa
    unsigned b1 = __float_as_uint(t1 + 12582912.0f);
    unsigned off0 = (b0 & 0xFF00u) << 1;             // word * 512 bytes
    unsigned off1 = (b1 & 0xFF00u) << 1;
    unsigned val0 = (b0 & 255u) * 65535u + 256u;     // (256-q) | (q<<16)
    unsigned val1 = (b1 & 255u) * 65535u + 256u;
    if (DIAG) {                                      // strict upper triangle
        if (iu >= jv)     off0 = 0u;                 // rare-test false...
        if (iu >= jv + 1) off1 = 0u;
        // ...and private write must be dead too:
        if (iu >= jv)     val0 = 0u;                 // 0 added to live word 0: no-op
        if (iu >= jv + 1) val1 = 0u;
    }
    // Rare fix-up FIRST (uses unmerged vals). Taken on ~0.3% of warp-batches.
    if (umax(off0, off1) > kLiveMax) {
        if (off0 > kLiveMax) {
            unsigned w = off0 >> 9;
            atomicAdd(rare + w,     val0 & 0xFFFFu);
            atomicAdd(rare + w + 1, val0 >> 16);
        }
        if (off1 > kLiveMax) {
            unsigned w = off1 >> 9;
            atomicAdd(rare + w,     val1 & 0xFFFFu);
            atomicAdd(rare + w + 1, val1 >> 16);
        }
    }
    // Private RMW: rare pairs self-clamp to dead word 134 via one umin.
    unsigned p0 = umin(off0, kDead134);
    unsigned p1 = umin(off1, kDead134);
    if (p0 == p1) { val0 += val1; p1 = kDead135; }   // no lost update
    unsigned a0 = *(unsigned*)(hb + p0);
    unsigned a1 = *(unsigned*)(hb + p1);
    *(unsigned*)(hb + p0) = a0 + val0;
    *(unsigned*)(hb + p1) = a1 + val1;
}

// ---------------------------------------------------------------------------
__global__ __launch_bounds__(kThreads, 3)
void pair_hist_kernel(float* __restrict__ out) {
    extern __shared__ unsigned int smem[];
    unsigned int* hist = smem;                         // [136][128]
    unsigned int* rare = smem + kHistU32;              // [208]
    float4* buf = (float4*)(rare + kRareU32);          // [256]

    const int s   = blockIdx.y;
    const int tid = threadIdx.x;
    const int tx  = tid & 15;     // cols tx*8 + v
    const int ty  = tid >> 4;     // rows ty*16 + u
    char* hb = (char*)hist + tid * 4;                  // bank = tid&31

#pragma unroll 4
    for (int w = 0; w < kWords; ++w) hist[(w << 7) + tid] = 0u;
    if (tid < kRareU32) rare[tid] = 0u;
    if (tid + kThreads < kRareU32) rare[tid + kThreads] = 0u;

    int p = blockIdx.x;
    int bi, bj;
    decode_tile(p, bi, bj);
    buf[tid]       = g_pos[s][bi * kTile + tid];
    buf[128 + tid] = g_pos[s][bj * kTile + tid];
    __syncthreads();

    for (;;) {
        const int pn = p + kBlocksX;
        const bool havenext = (pn < kNPairTiles);
        float4 na, nb; int bin_ = 0, bjn = 0;
        if (havenext) {                                // prefetch to registers
            decode_tile(pn, bin_, bjn);
            na = g_pos[s][bin_ * kTile + tid];
            nb = g_pos[s][bjn * kTile + tid];
        }

        const float4* ti = buf;
        const float4* tj = buf + 128;
        float4 rj[8];
#pragma unroll
        for (int v = 0; v < 8; ++v) rj[v] = tj[tx * 8 + v];

        if (bi != bj) {
            for (int u0 = 0; u0 < 16; u0 += 4) {
#pragma unroll
                for (int uu = 0; uu < 4; ++uu) {
                    float4 a4 = ti[ty * 16 + u0 + uu];
#pragma unroll
                    for (int v = 0; v < 8; v += 2)
                        process2<false>(hb, rare, a4.x, a4.y, a4.z, a4.w,
                                        rj[v], rj[v + 1], 0, 0);
                }
            }
        } else {
            for (int u0 = 0; u0 < 16; u0 += 4) {
#pragma unroll
                for (int uu = 0; uu < 4; ++uu) {
                    const int iu = ty * 16 + u0 + uu;
                    float4 a4 = ti[iu];
#pragma unroll
                    for (int v = 0; v < 8; v += 2)
                        process2<true>(hb, rare, a4.x, a4.y, a4.z, a4.w,
                                       rj[v], rj[v + 1], iu, tx * 8 + v);
                }
            }
        }

        __syncthreads();
        if (!havenext) break;
        buf[tid]       = na;
        buf[128 + tid] = nb;
        __syncthreads();
        p = pn; bi = bin_; bj = bjn;
    }

    // ---- flush ----
    // Private dual-field: word w low -> bin w, high -> bin w+1 (w 0..133;
    // words 134/135 dead). Rare flat bins 134..204 in rare[] (<=201 read).
    unsigned* slo = (unsigned*)buf;          // [136]
    unsigned* shi = slo + 136;               // [136]
#pragma unroll
    for (int c = 0; c < 2; ++c) {
        int w = tid + c * kThreads;
        if (w < kWords) {
            unsigned lo = 0, hi = 0;
            for (int i = 0; i < kThreads; ++i) {
                int t = (tid + i) & 127;                // staggered, conflict-free
                unsigned v = hist[(w << 7) + t];
                lo += v & 0xFFFFu;
                hi += v >> 16;
            }
            slo[w] = lo; shi[w] = hi;
        }
    }
    __syncthreads();
#pragma unroll
    for (int c = 0; c < 2; ++c) {
        int b = tid + c * kThreads;
        if (b <= 201) {
            unsigned tot = rare[b];                     // zero below 134
            if (b <= 133) tot += slo[b];
            if (b >= 1 && b <= 134) tot += shi[b - 1];
            int dst = (b == 201) ? 200 : b;             // fold 201 -> 200
            if (tot) atomicAdd(&g_hist[s][dst], tot);
        }
    }

    // ---- last block finalizes ----
    __threadfence();
    __shared__ unsigned int ticket;
    __syncthreads();
    if (tid == 0) ticket = atomicAdd(&g_done, 1u);
    __syncthreads();
    if (ticket != 2u * kBlocksX - 1u) return;
    __threadfence();

    double* sh = (double*)smem;
    volatile unsigned int* gh = (volatile unsigned int*)g_hist;
    double h0a = (tid < kNBins) ? (double)gh[tid] : 0.0;
    double h0b = (tid + 128 < kNBins) ? (double)gh[tid + 128] : 0.0;
    double h1a = (tid < kNBins) ? (double)gh[256 + tid] : 0.0;
    double h1b = (tid + 128 < kNBins) ? (double)gh[256 + tid + 128] : 0.0;

    sh[tid] = h0a + h0b; __syncthreads();
    for (int o = 64; o > 0; o >>= 1) { if (tid < o) sh[tid] += sh[tid + o]; __syncthreads(); }
    double s0 = sh[0]; __syncthreads();

    sh[tid] = h1a + h1b; __syncthreads();
    for (int o = 64; o > 0; o >>= 1) { if (tid < o) sh[tid] += sh[tid + o]; __syncthreads(); }
    double s1 = sh[0]; __syncthreads();

    double inv0 = 1.0 / (s0 + 1e-12), inv1 = 1.0 / (s1 + 1e-12);
    sh[tid] = fabs(h0a * inv0 - h1a * inv1) + fabs(h0b * inv0 - h1b * inv1);
    __syncthreads();
    for (int o = 64; o > 0; o >>= 1) { if (tid < o) sh[tid] += sh[tid + o]; __syncthreads(); }

    if (tid == 0) out[0] = (float)sh[0];
}

// ---------------------------------------------------------------------------
extern "C" void kernel_launch(void* const* d_in, const int* in_sizes, int n_in,
                              void* d_out, int out_size) {
    (void)in_sizes; (void)n_in; (void)out_size;
    const float* pred = (const float*)d_in[0];
    const float* tru  = (const float*)d_in[1];
    const float* mask = (const float*)d_in[2];

    cudaFuncSetAttribute(pair_hist_kernel,
                         cudaFuncAttributeMaxDynamicSharedMemorySize, kSmemBytes);

    prepack_kernel<<<(kNAtoms + 255) / 256, 256>>>(pred, tru, mask);

    dim3 grid(kBlocksX, 2);
    pair_hist_kernel<<<grid, kThreads, kSmemBytes>>>((float*)d_out);
}

// round 16
// speedup vs baseline: 1.2327x; 1.0489x over previous
#include <cuda_runtime.h>

// SAXS P(r) L1 loss — Round 12. Instruction diet on the R11 platform:
//  (1) fused magic rounding: clamp on g, b = fmaf(g, rsqrt(g), 1.5*2^23)
//      (saves FMUL+FADD, adds FMAX; net -1 FP/pair, single rounding);
//  (2) 256B word stride: two 64-lane thread groups each own half the
//      private hist -> offset = b & 0xFF00 with NO shift (saves 1 alu/pair);
//  (3) layout-adjusted rare path/flush. Same smem total (69632B hist),
//      3 blocks/SM, 1 RMW/pair, MLP=2 + equal-offset merge.

namespace {
constexpr int   kNBins      = 201;
constexpr int   kNAtoms     = 9472;                       // 256*37
constexpr int   kTile       = 128;
constexpr int   kNTiles     = kNAtoms / kTile;            // 74
constexpr int   kNPairTiles = kNTiles * (kNTiles + 1) / 2;   // 2775
constexpr int   kBlocksX    = 444;                        // 3 blocks/SM * 148
constexpr int   kThreads    = 128;
constexpr float kPre        = 724.0773439350246f;         // 512*sqrt(2)
constexpr float kGMax       = 2.7271e9f;                  // t<=52221 -> word<=203
constexpr int   kWords      = 136;   // 0..133 live, 134/135 dead
constexpr int   kGroupU32   = kWords * 64;                // 8704 u32 per group
constexpr int   kHistU32    = kGroupU32 * 2;              // 17408 (69632 B)
constexpr int   kRareU32    = 208;
constexpr int   kSmemBytes  = (kHistU32 + kRareU32) * 4 + 256 * 16;  // 74560
constexpr unsigned kLiveMax  = 34048u;   // 133*256
constexpr unsigned kDead134  = 34304u;   // 134*256 (umin clamp target)
constexpr unsigned kDead135  = 34560u;   // 135*256 (merge redirect)
}

__device__ float4       g_pos[2][kNAtoms];   // (x,y,z,|r|^2/2), prescaled
__device__ unsigned int g_hist[2][256];
__device__ unsigned int g_done;

// ---------------------------------------------------------------------------
__global__ void prepack_kernel(const float* __restrict__ pred,
                               const float* __restrict__ tru,
                               const float* __restrict__ mask) {
    int i = blockIdx.x * blockDim.x + threadIdx.x;
    if (i == 0) g_done = 0u;
    if (i < 512) ((unsigned int*)g_hist)[i] = 0u;
    if (i >= kNAtoms) return;
    float m = mask[i];
    if (m != 0.0f) {
        float px = pred[3*i+0]*kPre, py = pred[3*i+1]*kPre, pz = pred[3*i+2]*kPre;
        float qx = tru [3*i+0]*kPre, qy = tru [3*i+1]*kPre, qz = tru [3*i+2]*kPre;
        g_pos[0][i] = make_float4(px, py, pz, 0.5f * fmaf(px,px,fmaf(py,py,pz*pz)));
        g_pos[1][i] = make_float4(qx, qy, qz, 0.5f * fmaf(qx,qx,fmaf(qy,qy,qz*qz)));
    } else {
        float dx = 1.0e8f + (float)i * 2.0e5f;   // displaced -> g clamp -> word 203 (dropped)
        g_pos[0][i] = make_float4(dx, 0.f, 0.f, 0.5f * dx * dx);
        g_pos[1][i] = make_float4(dx, 0.f, 0.f, 0.5f * dx * dx);
    }
}

// ---------------------------------------------------------------------------
__device__ __forceinline__ void decode_tile(int p, int& bi, int& bj) {
    double Td = (double)kNTiles;
    int b = (int)(((2.0 * Td + 1.0) -
                   sqrt((2.0 * Td + 1.0) * (2.0 * Td + 1.0) - 8.0 * (double)p)) * 0.5);
    if (b < 0) b = 0;
    if (b > kNTiles - 1) b = kNTiles - 1;
    while (b * (2 * kNTiles - b + 1) / 2 > p) --b;
    while ((b + 1) * (2 * kNTiles - b) / 2 <= p) ++b;
    bi = b;
    bj = b + (p - b * (2 * kNTiles - b + 1) / 2);
}

// Two pairs. DIAG compile-time; iu/jv used only when DIAG.
template <bool DIAG>
__device__ __forceinline__ void process2(char* hb, unsigned* rare,
                                         float ax, float ay, float az, float aw,
                                         const float4 j0, const float4 j1,
                                         int iu, int jv) {
    float g0 = fmaf(ax, -j0.x, fmaf(ay, -j0.y, fmaf(az, -j0.z, aw + j0.w)));
    float g1 = fmaf(ax, -j1.x, fmaf(ay, -j1.y, fmaf(az, -j1.z, aw + j1.w)));
    g0 = fminf(fmaxf(g0, 1.0f), kGMax);              // >0 (rsqrt safe), NaN -> gmax
    g1 = fminf(fmaxf(g1, 1.0f), kGMax);
    // b = 12582912 + rn(sqrt(g)) in integer bits; sqrt(g) = 512*d = t
    unsigned b0 = __float_as_uint(fmaf(g0, rsqrtf(g0), 12582912.0f));
    unsigned b1 = __float_as_uint(fmaf(g1, rsqrtf(g1), 12582912.0f));
    unsigned off0 = b0 & 0xFF00u;                    // word * 256 bytes
    unsigned off1 = b1 & 0xFF00u;
    unsigned val0 = (b0 & 255u) * 65535u + 256u;     // (256-q) | (q<<16)
    unsigned val1 = (b1 & 255u) * 65535u + 256u;
    if (DIAG) {                                      // strict upper triangle
        if (iu >= jv)     { off0 = 0u; val0 = 0u; }  // +0 to live word 0: no-op
        if (iu >= jv + 1) { off1 = 0u; val1 = 0u; }
    }
    // Rare fix-up FIRST (unmerged vals); ~0.3% of warp-batches.
    if (umax(off0, off1) > kLiveMax) {
        if (off0 > kLiveMax) {
            unsigned w = off0 >> 8;
            atomicAdd(rare + w,     val0 & 0xFFFFu);
            atomicAdd(rare + w + 1, val0 >> 16);
        }
        if (off1 > kLiveMax) {
            unsigned w = off1 >> 8;
            atomicAdd(rare + w,     val1 & 0xFFFFu);
            atomicAdd(rare + w + 1, val1 >> 16);
        }
    }
    // Private RMW: rare pairs self-clamp to dead word 134 via one umin.
    unsigned p0 = umin(off0, kDead134);
    unsigned p1 = umin(off1, kDead134);
    if (p0 == p1) { val0 += val1; p1 = kDead135; }   // no lost update
    unsigned a0 = *(unsigned*)(hb + p0);
    unsigned a1 = *(unsigned*)(hb + p1);
    *(unsigned*)(hb + p0) = a0 + val0;
    *(unsigned*)(hb + p1) = a1 + val1;
}

// ---------------------------------------------------------------------------
__global__ __launch_bounds__(kThreads, 3)
void pair_hist_kernel(float* __restrict__ out) {
    extern __shared__ unsigned int smem[];
    unsigned int* hist = smem;                         // 2 groups x [136][64]
    unsigned int* rare = smem + kHistU32;              // [208]
    float4* buf = (float4*)(rare + kRareU32);          // [256]

    const int s   = blockIdx.y;
    const int tid = threadIdx.x;
    const int tx  = tid & 15;     // cols tx*8 + v
    const int ty  = tid >> 4;     // rows ty*16 + u
    // group (tid>>6) base + lane*4; word offset added as (b & 0xFF00)
    char* hb = (char*)hist + (tid >> 6) * (kGroupU32 * 4) + (tid & 63) * 4;

    for (int w = tid; w < kHistU32; w += kThreads) hist[w] = 0u;
    if (tid < kRareU32) rare[tid] = 0u;
    if (tid + kThreads < kRareU32) rare[tid + kThreads] = 0u;

    int p = blockIdx.x;
    int bi, bj;
    decode_tile(p, bi, bj);
    buf[tid]       = g_pos[s][bi * kTile + tid];
    buf[128 + tid] = g_pos[s][bj * kTile + tid];
    __syncthreads();

    for (;;) {
        const int pn = p + kBlocksX;
        const bool havenext = (pn < kNPairTiles);
        float4 na, nb; int bin_ = 0, bjn = 0;
        if (havenext) {                                // prefetch to registers
            decode_tile(pn, bin_, bjn);
            na = g_pos[s][bin_ * kTile + tid];
            nb = g_pos[s][bjn * kTile + tid];
        }

        const float4* ti = buf;
        const float4* tj = buf + 128;
        float4 rj[8];
#pragma unroll
        for (int v = 0; v < 8; ++v) rj[v] = tj[tx * 8 + v];

        if (bi != bj) {
            for (int u0 = 0; u0 < 16; u0 += 4) {
#pragma unroll
                for (int uu = 0; uu < 4; ++uu) {
                    float4 a4 = ti[ty * 16 + u0 + uu];
#pragma unroll
                    for (int v = 0; v < 8; v += 2)
                        process2<false>(hb, rare, a4.x, a4.y, a4.z, a4.w,
                                        rj[v], rj[v + 1], 0, 0);
                }
            }
        } else {
            for (int u0 = 0; u0 < 16; u0 += 4) {
#pragma unroll
                for (int uu = 0; uu < 4; ++uu) {
                    const int iu = ty * 16 + u0 + uu;
                    float4 a4 = ti[iu];
#pragma unroll
                    for (int v = 0; v < 8; v += 2)
                        process2<true>(hb, rare, a4.x, a4.y, a4.z, a4.w,
                                       rj[v], rj[v + 1], iu, tx * 8 + v);
                }
            }
        }

        __syncthreads();
        if (!havenext) break;
        buf[tid]       = na;
        buf[128 + tid] = nb;
        __syncthreads();
        p = pn; bi = bin_; bj = bjn;
    }

    // ---- flush ----
    // Private dual-field: word w low -> bin w, high -> bin w+1 (w 0..133;
    // words 134/135 dead). Rare flat bins 134..204 in rare[] (<=201 read).
    unsigned* slo = (unsigned*)buf;          // [136]
    unsigned* shi = slo + 136;               // [136]
#pragma unroll
    for (int c = 0; c < 2; ++c) {
        int w = tid + c * kThreads;
        if (w < kWords) {
            unsigned lo = 0, hi = 0;
            for (int i = 0; i < 64; ++i) {
                int l = (tid + i) & 63;                 // staggered
                unsigned v0 = hist[(w << 6) + l];             // group 0
                unsigned v1 = hist[kGroupU32 + (w << 6) + l]; // group 1
                lo += (v0 & 0xFFFFu) + (v1 & 0xFFFFu);
                hi += (v0 >> 16) + (v1 >> 16);
            }
            slo[w] = lo; shi[w] = hi;
        }
    }
    __syncthreads();
#pragma unroll
    for (int c = 0; c < 2; ++c) {
        int b = tid + c * kThreads;
        if (b <= 201) {
            unsigned tot = rare[b];                     // zero below 134
            if (b <= 133) tot += slo[b];
            if (b >= 1 && b <= 134) tot += shi[b - 1];
            int dst = (b == 201) ? 200 : b;             // fold 201 -> 200
            if (tot) atomicAdd(&g_hist[s][dst], tot);
        }
    }

    // ---- last block finalizes ----
    __threadfence();
    __shared__ unsigned int ticket;
    __syncthreads();
    if (tid == 0) ticket = atomicAdd(&g_done, 1u);
    __syncthreads();
    if (ticket != 2u * kBlocksX - 1u) return;
    __threadfence();

    double* sh = (double*)smem;
    volatile unsigned int* gh = (volatile unsigned int*)g_hist;
    double h0a = (tid < kNBins) ? (double)gh[tid] : 0.0;
    double h0b = (tid + 128 < kNBins) ? (double)gh[tid + 128] : 0.0;
    double h1a = (tid < kNBins) ? (double)gh[256 + tid] : 0.0;
    double h1b = (tid + 128 < kNBins) ? (double)gh[256 + tid + 128] : 0.0;

    sh[tid] = h0a + h0b; __syncthreads();
    for (int o = 64; o > 0; o >>= 1) { if (tid < o) sh[tid] += sh[tid + o]; __syncthreads(); }
    double s0 = sh[0]; __syncthreads();

    sh[tid] = h1a + h1b; __syncthreads();
    for (int o = 64; o > 0; o >>= 1) { if (tid < o) sh[tid] += sh[tid + o]; __syncthreads(); }
    double s1 = sh[0]; __syncthreads();

    double inv0 = 1.0 / (s0 + 1e-12), inv1 = 1.0 / (s1 + 1e-12);
    sh[tid] = fabs(h0a * inv0 - h1a * inv1) + fabs(h0b * inv0 - h1b * inv1);
    __syncthreads();
    for (int o = 64; o > 0; o >>= 1) { if (tid < o) sh[tid] += sh[tid + o]; __syncthreads(); }

    if (tid == 0) out[0] = (float)sh[0];
}

// ---------------------------------------------------------------------------
extern "C" void kernel_launch(void* const* d_in, const int* in_sizes, int n_in,
                              void* d_out, int out_size) {
    (void)in_sizes; (void)n_in; (void)out_size;
    const float* pred = (const float*)d_in[0];
    const float* tru  = (const float*)d_in[1];
    const float* mask = (const float*)d_in[2];

    cudaFuncSetAttribute(pair_hist_kernel,
                         cudaFuncAttributeMaxDynamicSharedMemorySize, kSmemBytes);

    prepack_kernel<<<(kNAtoms + 255) / 256, 256>>>(pred, tru, mask);

    dim3 grid(kBlocksX, 2);
    pair_hist_kernel<<<grid, kThreads, kSmemBytes>>>((float*)d_out);
}

// round 17
// speedup vs baseline: 1.3617x; 1.1046x over previous
#include <cuda_runtime.h>

// SAXS P(r) L1 loss — Round 13. Instruction diet, continued (R12 platform:
// 256B-stride dual-field private smem hist, 2x64-lane groups, 3 blocks/SM,
// fused magic rounding b = fmaf(g, rsqrt(g), 1.5*2^23)):
//  (1) MERGE REMOVED: per-pair RMWs are emitted sequentially; per-thread
//      same-address smem ordering makes lost updates impossible, no SETP/SEL.
//  (2) rare check amortized over 4 pairs (one umax tree + branch).
//  (3) tile (bi,bj) decode precomputed in prepack -> one LDG per tile instead
//      of DP sqrt + while loops.

namespace {
constexpr int   kNBins      = 201;
constexpr int   kNAtoms     = 9472;                       // 256*37
constexpr int   kTile       = 128;
constexpr int   kNTiles     = kNAtoms / kTile;            // 74
constexpr int   kNPairTiles = kNTiles * (kNTiles + 1) / 2;   // 2775
constexpr int   kBlocksX    = 444;                        // 3 blocks/SM * 148
constexpr int   kThreads    = 128;
constexpr float kPre        = 724.0773439350246f;         // 512*sqrt(2)
constexpr float kGMax       = 2.7271e9f;                  // t<=52221 -> word<=203
constexpr int   kWords      = 136;   // 0..133 live, 134 dead
constexpr int   kGroupU32   = kWords * 64;                // 8704 u32 per group
constexpr int   kHistU32    = kGroupU32 * 2;              // 17408 (69632 B)
constexpr int   kRareU32    = 208;
constexpr int   kSmemBytes  = (kHistU32 + kRareU32) * 4 + 256 * 16;  // 74560
constexpr unsigned kLiveMax  = 34048u;   // 133*256
constexpr unsigned kDead134  = 34304u;   // 134*256 (umin clamp target)
}

__device__ float4       g_pos[2][kNAtoms];   // (x,y,z,|r|^2/2), prescaled
__device__ unsigned int g_hist[2][256];
__device__ unsigned int g_tiles[kNPairTiles]; // bi<<16 | bj
__device__ unsigned int g_done;

// ---------------------------------------------------------------------------
__global__ void prepack_kernel(const float* __restrict__ pred,
                               const float* __restrict__ tru,
                               const float* __restrict__ mask) {
    int i = blockIdx.x * blockDim.x + threadIdx.x;
    if (i == 0) g_done = 0u;
    if (i < 512) ((unsigned int*)g_hist)[i] = 0u;
    if (i < kNPairTiles) {                    // decode upper-tri index -> (bi,bj)
        int b = 0;
        while ((b + 1) * (2 * kNTiles - b) / 2 <= i) ++b;
        int bj = b + (i - b * (2 * kNTiles - b + 1) / 2);
        g_tiles[i] = ((unsigned)b << 16) | (unsigned)bj;
    }
    if (i >= kNAtoms) return;
    float m = mask[i];
    if (m != 0.0f) {
        float px = pred[3*i+0]*kPre, py = pred[3*i+1]*kPre, pz = pred[3*i+2]*kPre;
        float qx = tru [3*i+0]*kPre, qy = tru [3*i+1]*kPre, qz = tru [3*i+2]*kPre;
        g_pos[0][i] = make_float4(px, py, pz, 0.5f * fmaf(px,px,fmaf(py,py,pz*pz)));
        g_pos[1][i] = make_float4(qx, qy, qz, 0.5f * fmaf(qx,qx,fmaf(qy,qy,qz*qz)));
    } else {
        float dx = 1.0e8f + (float)i * 2.0e5f;   // displaced -> g clamp -> dropped
        g_pos[0][i] = make_float4(dx, 0.f, 0.f, 0.5f * dx * dx);
        g_pos[1][i] = make_float4(dx, 0.f, 0.f, 0.5f * dx * dx);
    }
}

// ---------------------------------------------------------------------------
// Four pairs: one i-atom vs 4 j-atoms. DIAG compile-time.
// Sequential RMWs (no merge needed: per-thread smem ordering is coherent).
template <bool DIAG>
__device__ __forceinline__ void process4(char* hb, unsigned* rare,
                                         float ax, float ay, float az, float aw,
                                         const float4* rj, int v0,
                                         int iu, int jv) {
    unsigned off[4], val[4];
#pragma unroll
    for (int k = 0; k < 4; ++k) {
        const float4 j = rj[v0 + k];
        float g = fmaf(ax, -j.x, fmaf(ay, -j.y, fmaf(az, -j.z, aw + j.w)));
        g = fminf(fmaxf(g, 1.0f), kGMax);            // rsqrt-safe, NaN -> gmax
        unsigned b = __float_as_uint(fmaf(g, rsqrtf(g), 12582912.0f)); // rn(512d)
        off[k] = b & 0xFF00u;                        // word * 256 bytes
        val[k] = (b & 255u) * 65535u + 256u;         // (256-q) | (q<<16)
        if (DIAG) {
            if (iu >= jv + k) { off[k] = 0u; val[k] = 0u; }  // +0: no-op
        }
    }
    // Rare fix-up once per 4 pairs (~0.6% of warp-batches taken).
    if (umax(umax(off[0], off[1]), umax(off[2], off[3])) > kLiveMax) {
#pragma unroll
        for (int k = 0; k < 4; ++k) {
            if (off[k] > kLiveMax) {
                unsigned w = off[k] >> 8;
                atomicAdd(rare + w,     val[k] & 0xFFFFu);
                atomicAdd(rare + w + 1, val[k] >> 16);
            }
        }
    }
#pragma unroll
    for (int k = 0; k < 4; ++k) {
        unsigned p = umin(off[k], kDead134);         // rare -> dead word 134
        *(unsigned*)(hb + p) += val[k];              // ordered per thread: safe
    }
}

// ---------------------------------------------------------------------------
__global__ __launch_bounds__(kThreads, 3)
void pair_hist_kernel(float* __restrict__ out) {
    extern __shared__ unsigned int smem[];
    unsigned int* hist = smem;                         // 2 groups x [136][64]
    unsigned int* rare = smem + kHistU32;              // [208]
    float4* buf = (float4*)(rare + kRareU32);          // [256]

    const int s   = blockIdx.y;
    const int tid = threadIdx.x;
    const int tx  = tid & 15;     // cols tx*8 + v
    const int ty  = tid >> 4;     // rows ty*16 + u
    char* hb = (char*)hist + (tid >> 6) * (kGroupU32 * 4) + (tid & 63) * 4;

    for (int w = tid; w < kHistU32; w += kThreads) hist[w] = 0u;
    if (tid < kRareU32) rare[tid] = 0u;
    if (tid + kThreads < kRareU32) rare[tid + kThreads] = 0u;

    int p = blockIdx.x;
    unsigned te = g_tiles[p];
    int bi = te >> 16, bj = te & 0xFFFF;
    buf[tid]       = g_pos[s][bi * kTile + tid];
    buf[128 + tid] = g_pos[s][bj * kTile + tid];
    __syncthreads();

    for (;;) {
        const int pn = p + kBlocksX;
        const bool havenext = (pn < kNPairTiles);
        float4 na, nb; int bin_ = 0, bjn = 0;
        if (havenext) {                                // prefetch to registers
            unsigned tn = g_tiles[pn];
            bin_ = tn >> 16; bjn = tn & 0xFFFF;
            na = g_pos[s][bin_ * kTile + tid];
            nb = g_pos[s][bjn * kTile + tid];
        }

        const float4* ti = buf;
        const float4* tj = buf + 128;
        float4 rj[8];
#pragma unroll
        for (int v = 0; v < 8; ++v) rj[v] = tj[tx * 8 + v];

        if (bi != bj) {
            for (int u0 = 0; u0 < 16; u0 += 4) {
#pragma unroll
                for (int uu = 0; uu < 4; ++uu) {
                    float4 a4 = ti[ty * 16 + u0 + uu];
                    process4<false>(hb, rare, a4.x, a4.y, a4.z, a4.w, rj, 0, 0, 0);
                    process4<false>(hb, rare, a4.x, a4.y, a4.z, a4.w, rj, 4, 0, 0);
                }
            }
        } else {
            for (int u0 = 0; u0 < 16; u0 += 4) {
#pragma unroll
                for (int uu = 0; uu < 4; ++uu) {
                    const int iu = ty * 16 + u0 + uu;
                    float4 a4 = ti[iu];
                    process4<true>(hb, rare, a4.x, a4.y, a4.z, a4.w, rj, 0,
                                   iu, tx * 8);
                    process4<true>(hb, rare, a4.x, a4.y, a4.z, a4.w, rj, 4,
                                   iu, tx * 8 + 4);
                }
            }
        }

        __syncthreads();
        if (!havenext) break;
        buf[tid]       = na;
        buf[128 + tid] = nb;
        __syncthreads();
        p = pn; bi = bin_; bj = bjn;
    }

    // ---- flush ----
    // Private dual-field: word w low -> bin w, high -> bin w+1 (w 0..133;
    // word 134 dead). Rare flat bins 134..204 in rare[] (reads <= 201).
    unsigned* slo = (unsigned*)buf;          // [136]
    unsigned* shi = slo + 136;               // [136]
#pragma unroll
    for (int c = 0; c < 2; ++c) {
        int w = tid + c * kThreads;
        if (w < kWords) {
            unsigned lo = 0, hi = 0;
            for (int i = 0; i < 64; ++i) {
                int l = (tid + i) & 63;                 // staggered
                unsigned v0 = hist[(w << 6) + l];             // group 0
                unsigned v1 = hist[kGroupU32 + (w << 6) + l]; // group 1
                lo += (v0 & 0xFFFFu) + (v1 & 0xFFFFu);
                hi += (v0 >> 16) + (v1 >> 16);
            }
            slo[w] = lo; shi[w] = hi;
        }
    }
    __syncthreads();
#pragma unroll
    for (int c = 0; c < 2; ++c) {
        int b = tid + c * kThreads;
        if (b <= 201) {
            unsigned tot = rare[b];                     // zero below 134
            if (b <= 133) tot += slo[b];
            if (b >= 1 && b <= 134) tot += shi[b - 1];
            int dst = (b == 201) ? 200 : b;             // fold 201 -> 200
            if (tot) atomicAdd(&g_hist[s][dst], tot);
        }
    }

    // ---- last block finalizes ----
    __threadfence();
    __shared__ unsigned int ticket;
    __syncthreads();
    if (tid == 0) ticket = atomicAdd(&g_done, 1u);
    __syncthreads();
    if (ticket != 2u * kBlocksX - 1u) return;
    __threadfence();

    double* sh = (double*)smem;
    volatile unsigned int* gh = (volatile unsigned int*)g_hist;
    double h0a = (tid < kNBins) ? (double)gh[tid] : 0.0;
    double h0b = (tid + 128 < kNBins) ? (double)gh[tid + 128] : 0.0;
    double h1a = (tid < kNBins) ? (double)gh[256 + tid] : 0.0;
    double h1b = (tid + 128 < kNBins) ? (double)gh[256 + tid + 128] : 0.0;

    sh[tid] = h0a + h0b; __syncthreads();
    for (int o = 64; o > 0; o >>= 1) { if (tid < o) sh[tid] += sh[tid + o]; __syncthreads(); }
    double s0 = sh[0]; __syncthreads();

    sh[tid] = h1a + h1b; __syncthreads();
    for (int o = 64; o > 0; o >>= 1) { if (tid < o) sh[tid] += sh[tid + o]; __syncthreads(); }
    double s1 = sh[0]; __syncthreads();

    double inv0 = 1.0 / (s0 + 1e-12), inv1 = 1.0 / (s1 + 1e-12);
    sh[tid] = fabs(h0a * inv0 - h1a * inv1) + fabs(h0b * inv0 - h1b * inv1);
    __syncthreads();
    for (int o = 64; o > 0; o >>= 1) { if (tid < o) sh[tid] += sh[tid + o]; __syncthreads(); }

    if (tid == 0) out[0] = (float)sh[0];
}

// ---------------------------------------------------------------------------
extern "C" void kernel_launch(void* const* d_in, const int* in_sizes, int n_in,
                              void* d_out, int out_size) {
    (void)in_sizes; (void)n_in; (void)out_size;
    const float* pred = (const float*)d_in[0];
    const float* tru  = (const float*)d_in[1];
    const float* mask = (const float*)d_in[2];

    cudaFuncSetAttribute(pair_hist_kernel,
                         cudaFuncAttributeMaxDynamicSharedMemorySize, kSmemBytes);

    prepack_kernel<<<(kNAtoms + 255) / 256, 256>>>(pred, tru, mask);

    dim3 grid(kBlocksX, 2);
    pair_hist_kernel<<<grid, kThreads, kSmemBytes>>>((float*)d_out);
}